// round 14
// baseline (speedup 1.0000x reference)
#include <cuda_runtime.h>
#include <cuda_fp16.h>
#include <cstdint>

#define NN 200000
#define NE 400000
#define HS 128
#define ROW_TILES 1563            // ceil(200000/128)
#define NPAD (ROW_TILES * 128)    // 200064 padded rows

#define TSZ 32768                 // bytes per swizzled [128x128] fp16 tile
#define SMEM_MMA (3 * TSZ)        // A hi/lo + B single buffer = 98304 B

// ---------------- scratch (device globals; no allocs allowed) ----------------
// NOTE: never passed as kernel args from host (host shadow + ATS trap);
// all resolution happens inside device code via `sel`.
__device__ float g_xall[(size_t)NN * 384];   // i|o|u pre-activations; sel0 writes x-part,
                                             // sel2 accumulates uh-part IN PLACE
__device__ __align__(16) __half g_xf16[(size_t)NPAD * HS];  // x@w_f^T + b_f (fp16)
__device__ __align__(16) __half g_hu16[(size_t)NPAD * HS];  // h_child @ u_f^T (fp16)
__device__ float g_hsum[(size_t)NN * HS];    // segsum(h_child[src])    [N,128]
__device__ float g_fcsum[(size_t)NN * HS];   // segsum(f*c_child[src])  [N,128]
// pre-split fp16 A operands: A = hi + lo (22-bit effective mantissa)
__device__ __align__(16) __half g_xhi[(size_t)NPAD * HS];
__device__ __align__(16) __half g_xlo[(size_t)NPAD * HS];
__device__ __align__(16) __half g_hhi[(size_t)NPAD * HS];
__device__ __align__(16) __half g_hlo[(size_t)NPAD * HS];
__device__ __align__(16) __half g_shi[(size_t)NPAD * HS];
__device__ __align__(16) __half g_slo[(size_t)NPAD * HS];
// packed fp16 weights (hi only), 8 tiles of [128 n][128 k] row-major:
// tiles 0-3: [w_iou;w_f] (512 rows: 0=i,1=o,2=u,3=f), 4-6: u_iou (4=i,5=o,6=u), 7: u_f
__device__ __align__(16) __half g_Bhi[8 * 16384];
__device__ __align__(16) float g_bias[512];

__device__ __forceinline__ float sigmoidf(float v) { return 1.0f / (1.0f + __expf(-v)); }

__device__ __forceinline__ uint32_t smem_u32(const void* p) {
    uint32_t a;
    asm("{ .reg .u64 t; cvta.to.shared.u64 t, %1; cvt.u32.u64 %0, t; }" : "=r"(a) : "l"(p));
    return a;
}

__device__ __forceinline__ void ldsm4(uint32_t* r, uint32_t addr) {
    asm volatile("ldmatrix.sync.aligned.m8n8.x4.shared.b16 {%0,%1,%2,%3}, [%4];"
                 : "=r"(r[0]), "=r"(r[1]), "=r"(r[2]), "=r"(r[3]) : "r"(addr));
}

__device__ __forceinline__ void mma16816(float* c, const uint32_t* a, uint32_t b0, uint32_t b1) {
    asm volatile(
        "mma.sync.aligned.m16n8k16.row.col.f32.f16.f16.f32 "
        "{%0,%1,%2,%3}, {%4,%5,%6,%7}, {%8,%9}, {%0,%1,%2,%3};"
        : "+f"(c[0]), "+f"(c[1]), "+f"(c[2]), "+f"(c[3])
        : "r"(a[0]), "r"(a[1]), "r"(a[2]), "r"(a[3]), "r"(b0), "r"(b1));
}

__device__ __forceinline__ void cp16(uint32_t dst, const void* src) {
    asm volatile("cp.async.cg.shared.global [%0], [%1], 16;" :: "r"(dst), "l"(src));
}
__device__ __forceinline__ void cp_commit() {
    asm volatile("cp.async.commit_group;");
}
template <int N>
__device__ __forceinline__ void cp_wait() {
    asm volatile("cp.async.wait_group %0;" :: "n"(N));
}

__device__ __forceinline__ uint32_t pack2h(__half lo, __half hi) {
    return (uint32_t)__half_as_ushort(lo) | ((uint32_t)__half_as_ushort(hi) << 16);
}

// ---------------- split fp32 -> fp16 hi/lo (4 elems per thread) ----------------
// sel 0: src=ext (x)       -> g_xhi/g_xlo   (+ zero g_hsum/g_fcsum)
// sel 1: src=ext (h_child) -> g_hhi/g_hlo
// sel 2: src=g_hsum        -> g_shi/g_slo
__global__ void k_split(const float* __restrict__ ext, int sel) {
    const int total4 = NN * HS / 4;
    int i = blockIdx.x * blockDim.x + threadIdx.x;
    if (i >= total4) return;
    const float* src = (sel == 2) ? g_hsum : ext;
    __half* hi = (sel == 0) ? g_xhi : (sel == 1) ? g_hhi : g_shi;
    __half* lo = (sel == 0) ? g_xlo : (sel == 1) ? g_hlo : g_slo;
    if (sel == 0) {
        float4 z = make_float4(0.f, 0.f, 0.f, 0.f);
        reinterpret_cast<float4*>(g_hsum)[i] = z;
        reinterpret_cast<float4*>(g_fcsum)[i] = z;
    }
    float4 v = reinterpret_cast<const float4*>(src)[i];
    float f[4] = {v.x, v.y, v.z, v.w};
    uint32_t hp[2], lp[2];
#pragma unroll
    for (int p = 0; p < 2; p++) {
        __half h0 = __float2half_rn(f[2 * p]);
        __half h1 = __float2half_rn(f[2 * p + 1]);
        __half l0 = __float2half_rn(f[2 * p] - __half2float(h0));
        __half l1 = __float2half_rn(f[2 * p + 1] - __half2float(h1));
        hp[p] = pack2h(h0, h1);
        lp[p] = pack2h(l0, l1);
    }
    reinterpret_cast<uint2*>(hi)[i] = make_uint2(hp[0], hp[1]);
    reinterpret_cast<uint2*>(lo)[i] = make_uint2(lp[0], lp[1]);
}

// ---------------- pack weights: fp32 -> fp16, row-major [n][k] tiles ----------------
__global__ void k_prep(const float* __restrict__ w_iou, const float* __restrict__ w_f,
                       const float* __restrict__ u_iou, const float* __restrict__ u_f,
                       const float* __restrict__ b_iou, const float* __restrict__ b_f) {
    int i = blockIdx.x * blockDim.x + threadIdx.x;
    if (i < 512) g_bias[i] = (i < 384) ? b_iou[i] : b_f[i - 384];
    if (i >= 131072) return;
    int n, k, tile;
    float val;
    if (i < 65536) {                       // [w_iou ; w_f], 512 rows
        n = i >> 7; k = i & 127;
        tile = n >> 7;
        val = (n < 384) ? w_iou[n * 128 + k] : w_f[(n - 384) * 128 + k];
    } else if (i < 65536 + 49152) {        // u_iou, 384 rows
        int j = i - 65536;
        n = j >> 7; k = j & 127;
        tile = 4 + (n >> 7);
        val = u_iou[n * 128 + k];
    } else {                               // u_f, 128 rows
        int j = i - 114688;
        n = j >> 7; k = j & 127;
        tile = 7;
        val = u_f[n * 128 + k];
    }
    g_Bhi[tile * 16384 + (n & 127) * 128 + k] = __float2half_rn(val);
}

// swizzled byte offset of 16B chunk (r, c) in a [128 rows x 16 chunks] tile
__device__ __forceinline__ uint32_t sw_chunk(int r, int c) {
    return (uint32_t)(r * 256 + ((c ^ (r & 7)) << 4));
}

// copy one [128][128] fp16 tile, global row-major -> swizzled smem, via cp.async
__device__ __forceinline__ void copy_tile(uint32_t sdst, const __half* gsrc, int tid) {
#pragma unroll
    for (int it = 0; it < 8; it++) {
        int j = tid + it * 256;        // 2048 16B chunks
        int r = j >> 4, c = j & 15;
        cp16(sdst + sw_chunk(r, c), gsrc + r * 128 + c * 8);
    }
}

// ============================================================================
// fp16 mma.sync GEMM, 2-term split: D = Ahi*Bhi + Alo*Bhi.
// Swizzled 32KB tiles; A hi/lo + single B = 96KB -> 2 CTAs/SM.
// 256 threads, warp grid 4x2, warp tile 32x64 (R11-proven core).
// sel 0: x -> g_xall (i,o,u fp32, +bias) + g_xf16 (f, fp16, +bias)
// sel 1: h_child -> g_hu16 (fp16)
// sel 2: hsum -> ACCUMULATE into g_xall in place (3 tiles), then fused node
//        update for this CTA's 128 rows (writes h,c to out; k_final deleted)
// ============================================================================
__global__ void __launch_bounds__(256, 2) k_mma(int sel, float* __restrict__ out) {
    const __half* Ahi = (sel == 0) ? g_xhi : (sel == 1) ? g_hhi : g_shi;
    const __half* Alo = (sel == 0) ? g_xlo : (sel == 1) ? g_hlo : g_slo;
    const int first  = (sel == 0) ? 0 : (sel == 1) ? 7 : 4;
    const int ntiles = (sel == 0) ? 4 : (sel == 1) ? 1 : 3;

    extern __shared__ __half sm[];
    const int tid = threadIdx.x;
    const int lane = tid & 31, wid = tid >> 5;
    const int brow = blockIdx.x * 128;

    const uint32_t sA = smem_u32(sm);            // A hi; lo at +TSZ
    const uint32_t sB = sA + 2 * TSZ;            // single B buffer

    copy_tile(sA, Ahi + (size_t)brow * 128, tid);
    copy_tile(sA + TSZ, Alo + (size_t)brow * 128, tid);
    copy_tile(sB, g_Bhi + (size_t)first * 16384, tid);
    cp_commit();

    // ---- warp tiling: 4x2 warps, each 32 rows x 64 cols ----
    const int wr = wid & 3;
    const int wcol = wid >> 2;
    const int aRow = wr * 32 + (lane & 15);
    const int c0a  = lane >> 4;
    const int rma  = aRow & 7;
    const int gg   = lane >> 3;
    const int bRow = wcol * 64 + (gg >> 1) * 8 + (lane & 7);
    const int c0b  = gg & 1;
    const int rmb  = bRow & 7;

    const uint32_t aBase0 = sA + (uint32_t)aRow * 256;
    const uint32_t aBase1 = aBase0 + 16 * 256;
    const uint32_t bBase  = sB + (uint32_t)bRow * 256;

    for (int t = 0; t < ntiles; t++) {
        cp_wait<0>();
        __syncthreads();

        float acc[2][8][4];
#pragma unroll
        for (int i = 0; i < 2; i++)
#pragma unroll
            for (int j = 0; j < 8; j++)
#pragma unroll
                for (int q = 0; q < 4; q++) acc[i][j][q] = 0.f;

#pragma unroll
        for (int kb = 0; kb < 8; kb++) {
            const uint32_t ca = (uint32_t)(((c0a + 2 * kb) ^ rma) << 4);
            const uint32_t cb = (uint32_t)(((c0b + 2 * kb) ^ rmb) << 4);
            uint32_t aH[2][4], aL[2][4];
            ldsm4(aH[0], aBase0 + ca);
            ldsm4(aH[1], aBase1 + ca);
            ldsm4(aL[0], aBase0 + TSZ + ca);
            ldsm4(aL[1], aBase1 + TSZ + ca);
            uint32_t b[4][4];
#pragma unroll
            for (int p = 0; p < 4; p++)
                ldsm4(b[p], bBase + p * 16 * 256 + cb);
#pragma unroll
            for (int i = 0; i < 2; i++)
#pragma unroll
                for (int j = 0; j < 8; j++) {
                    uint32_t b0 = b[j >> 1][(j & 1) * 2], b1 = b[j >> 1][(j & 1) * 2 + 1];
                    mma16816(acc[i][j], aH[i], b0, b1);
                    mma16816(acc[i][j], aL[i], b0, b1);
                }
        }

        __syncthreads();
        if (t + 1 < ntiles) {                  // overlap next-B load with epilogue
            copy_tile(sB, g_Bhi + (size_t)(first + t + 1) * 16384, tid);
            cp_commit();
        }

        // ---- epilogue for this column tile ----
        const bool ftile = (sel == 0) && (t == 3);
        const int colb = ((sel == 0 && t < 3) || sel == 2) ? (t * 128 + wcol * 64)
                                                           : (wcol * 64);
        const int biasb = (sel == 0) ? (((t < 3) ? t * 128 : 384) + wcol * 64) : 0;
#pragma unroll
        for (int i = 0; i < 2; i++) {
            int row0 = brow + wr * 32 + i * 16 + (lane >> 2);
            int row1 = row0 + 8;
#pragma unroll
            for (int j = 0; j < 8; j++) {
                int cj = j * 8 + (lane & 3) * 2;
                float bx = 0.f, by = 0.f;
                if (sel == 0) { bx = g_bias[biasb + cj]; by = g_bias[biasb + cj + 1]; }
#pragma unroll
                for (int h2 = 0; h2 < 2; h2++) {
                    int grow = h2 ? row1 : row0;
                    if (grow >= NN) continue;
                    float v0 = acc[i][j][h2 * 2] + bx;
                    float v1 = acc[i][j][h2 * 2 + 1] + by;
                    if (sel == 1) {
                        *reinterpret_cast<__half2*>(g_hu16 + (size_t)grow * HS + colb + cj) =
                            __floats2half2_rn(v0, v1);
                    } else if (ftile) {
                        *reinterpret_cast<__half2*>(g_xf16 + (size_t)grow * HS + (wcol * 64) + cj) =
                            __floats2half2_rn(v0, v1);
                    } else if (sel == 0) {
                        *reinterpret_cast<float2*>(g_xall + (size_t)grow * 384 + colb + cj) =
                            make_float2(v0, v1);
                    } else {
                        // sel 2: accumulate uh into xall in place
                        float* p = g_xall + (size_t)grow * 384 + colb + cj;
                        float2 prev = *reinterpret_cast<float2*>(p);
                        *reinterpret_cast<float2*>(p) =
                            make_float2(prev.x + v0, prev.y + v1);
                    }
                }
            }
        }
    }

    // ---- sel 2 tail: fused node update for this CTA's rows ----
    // All 3 gate tiles for rows [brow, brow+128) were summed by THIS CTA above;
    // __syncthreads gives block-scope visibility of those global writes, and the
    // slice (192KB) is L2-hot.
    if (sel == 2) {
        __syncthreads();
        for (int it = tid; it < 128 * 64; it += 256) {   // float2 granularity
            int rl = it >> 6;
            int grow = brow + rl;
            if (grow >= NN) continue;
            int cj = (it & 63) * 2;
            const float* xr = g_xall + (size_t)grow * 384;
            float2 pi = *reinterpret_cast<const float2*>(xr + cj);
            float2 po = *reinterpret_cast<const float2*>(xr + 128 + cj);
            float2 pu = *reinterpret_cast<const float2*>(xr + 256 + cj);
            float2 fc = *reinterpret_cast<const float2*>(g_fcsum + (size_t)grow * HS + cj);
            float c0 = sigmoidf(pi.x) * tanhf(pu.x) + fc.x;
            float c1 = sigmoidf(pi.y) * tanhf(pu.y) + fc.y;
            float h0 = sigmoidf(po.x) * tanhf(c0);
            float h1 = sigmoidf(po.y) * tanhf(c1);
            *reinterpret_cast<float2*>(out + (size_t)grow * HS + cj) = make_float2(h0, h1);
            *reinterpret_cast<float2*>(out + (size_t)NN * HS + (size_t)grow * HS + cj) =
                make_float2(c0, c1);
        }
    }
}

// ---------------- edge pass: one warp per edge, fp16 hu/xf gathers ----------------
__global__ void k_edge(const float* __restrict__ h_child, const float* __restrict__ c_child,
                       const int* __restrict__ esrc, const int* __restrict__ edst) {
    int idx = blockIdx.x * blockDim.x + threadIdx.x;
    int e = idx >> 5;
    int q = idx & 31;
    if (e >= NE) return;
    int s = esrc[e];
    int d = edst[e];
    float4 h4 = reinterpret_cast<const float4*>(h_child + (size_t)s * HS)[q];
    float4 c4 = reinterpret_cast<const float4*>(c_child + (size_t)s * HS)[q];
    const __half2* hu2 = reinterpret_cast<const __half2*>(g_hu16 + (size_t)s * HS + q * 4);
    const __half2* xf2 = reinterpret_cast<const __half2*>(g_xf16 + (size_t)d * HS + q * 4);
    float2 huA = __half22float2(hu2[0]), huB = __half22float2(hu2[1]);
    float2 xfA = __half22float2(xf2[0]), xfB = __half22float2(xf2[1]);
    float* hs = g_hsum + (size_t)d * HS + q * 4;
    float* fc = g_fcsum + (size_t)d * HS + q * 4;
    atomicAdd(hs + 0, h4.x); atomicAdd(hs + 1, h4.y);
    atomicAdd(hs + 2, h4.z); atomicAdd(hs + 3, h4.w);
    atomicAdd(fc + 0, sigmoidf(xfA.x + huA.x) * c4.x);
    atomicAdd(fc + 1, sigmoidf(xfA.y + huA.y) * c4.y);
    atomicAdd(fc + 2, sigmoidf(xfB.x + huB.x) * c4.z);
    atomicAdd(fc + 3, sigmoidf(xfB.y + huB.y) * c4.w);
}

// ============================================================================
extern "C" void kernel_launch(void* const* d_in, const int* in_sizes, int n_in,
                              void* d_out, int out_size) {
    const float* x       = (const float*)d_in[0];
    const float* h_child = (const float*)d_in[1];
    const float* c_child = (const float*)d_in[2];
    const float* w_iou   = (const float*)d_in[3];
    const float* b_iou   = (const float*)d_in[4];
    const float* w_f     = (const float*)d_in[5];
    const float* b_f     = (const float*)d_in[6];
    const float* u_iou   = (const float*)d_in[7];
    const float* u_f     = (const float*)d_in[8];
    const int*   esrc    = (const int*)d_in[9];
    const int*   edst    = (const int*)d_in[10];
    float* out = (float*)d_out;

    static bool configured = false;
    if (!configured) {
        cudaFuncSetAttribute(k_mma, cudaFuncAttributeMaxDynamicSharedMemorySize, SMEM_MMA);
        configured = true;
    }

    const int total4 = NN * HS / 4;
    const int sgrid = (total4 + 255) / 256;

    k_prep<<<131072 / 256, 256>>>(w_iou, w_f, u_iou, u_f, b_iou, b_f);
    k_split<<<sgrid, 256>>>(x, 0);                 // also zeroes g_hsum/g_fcsum
    k_split<<<sgrid, 256>>>(h_child, 1);
    k_mma<<<ROW_TILES, 256, SMEM_MMA>>>(0, out);   // x -> g_xall (i|o|u) + g_xf16 (f)
    k_mma<<<ROW_TILES, 256, SMEM_MMA>>>(1, out);   // h_child -> g_hu16
    k_edge<<<(NE * 32) / 256, 256>>>(h_child, c_child, esrc, edst);
    k_split<<<sgrid, 256>>>(nullptr, 2);           // g_hsum -> g_shi/g_slo
    k_mma<<<ROW_TILES, 256, SMEM_MMA>>>(2, out);   // uh += ; fused node update -> out
}

// round 15
// speedup vs baseline: 1.2429x; 1.2429x over previous
#include <cuda_runtime.h>
#include <cuda_fp16.h>
#include <cstdint>

#define NN 200000
#define NE 400000
#define HS 128
#define ROW_TILES 1563            // ceil(200000/128)
#define NPAD (ROW_TILES * 128)    // 200064 padded rows

#define TSZ 32768                 // bytes per swizzled [128x128] fp16 tile
#define SMEM_MMA (3 * TSZ)        // A hi/lo + B single buffer = 98304 B

// ---------------- scratch (device globals; no allocs allowed) ----------------
// NOTE: never passed as kernel args from host (host shadow + ATS trap);
// all resolution happens inside device code via `sel`.
__device__ float g_xall[(size_t)NN * 384];   // x@w_iou^T + b_iou   [N,384] = i|o|u (fp32)
__device__ float g_uhsum[(size_t)NN * 384];  // hsum @ u_iou^T      [N,384] (fp32)
__device__ __align__(16) __half g_xf16[(size_t)NPAD * HS];  // x@w_f^T + b_f (fp16)
__device__ __align__(16) __half g_hu16[(size_t)NPAD * HS];  // h_child @ u_f^T (fp16)
// hsum accumulated DIRECTLY in fp16 (half2 atomics); it is also the GEMM A
// operand for sel2 (exactly representable -> single-term MMA, no lo tile).
__device__ __align__(16) __half g_hsum16[(size_t)NPAD * HS];
__device__ float g_fcsum[(size_t)NN * HS];   // segsum(f*c_child[src])  [N,128] (fp32)
// pre-split fp16 A operands: A = hi + lo (22-bit effective mantissa)
__device__ __align__(16) __half g_xhi[(size_t)NPAD * HS];
__device__ __align__(16) __half g_xlo[(size_t)NPAD * HS];
__device__ __align__(16) __half g_hhi[(size_t)NPAD * HS];
__device__ __align__(16) __half g_hlo[(size_t)NPAD * HS];
// packed fp16 weights (hi only), 8 tiles of [128 n][128 k] row-major:
// tiles 0-3: [w_iou;w_f] (512 rows: 0=i,1=o,2=u,3=f), 4-6: u_iou (4=i,5=o,6=u), 7: u_f
__device__ __align__(16) __half g_Bhi[8 * 16384];
__device__ __align__(16) float g_bias[512];

__device__ __forceinline__ float sigmoidf(float v) { return 1.0f / (1.0f + __expf(-v)); }

__device__ __forceinline__ uint32_t smem_u32(const void* p) {
    uint32_t a;
    asm("{ .reg .u64 t; cvta.to.shared.u64 t, %1; cvt.u32.u64 %0, t; }" : "=r"(a) : "l"(p));
    return a;
}

__device__ __forceinline__ void ldsm4(uint32_t* r, uint32_t addr) {
    asm volatile("ldmatrix.sync.aligned.m8n8.x4.shared.b16 {%0,%1,%2,%3}, [%4];"
                 : "=r"(r[0]), "=r"(r[1]), "=r"(r[2]), "=r"(r[3]) : "r"(addr));
}

__device__ __forceinline__ void mma16816(float* c, const uint32_t* a, uint32_t b0, uint32_t b1) {
    asm volatile(
        "mma.sync.aligned.m16n8k16.row.col.f32.f16.f16.f32 "
        "{%0,%1,%2,%3}, {%4,%5,%6,%7}, {%8,%9}, {%0,%1,%2,%3};"
        : "+f"(c[0]), "+f"(c[1]), "+f"(c[2]), "+f"(c[3])
        : "r"(a[0]), "r"(a[1]), "r"(a[2]), "r"(a[3]), "r"(b0), "r"(b1));
}

__device__ __forceinline__ void cp16(uint32_t dst, const void* src) {
    asm volatile("cp.async.cg.shared.global [%0], [%1], 16;" :: "r"(dst), "l"(src));
}
__device__ __forceinline__ void cp_commit() {
    asm volatile("cp.async.commit_group;");
}
template <int N>
__device__ __forceinline__ void cp_wait() {
    asm volatile("cp.async.wait_group %0;" :: "n"(N));
}

__device__ __forceinline__ uint32_t pack2h(__half lo, __half hi) {
    return (uint32_t)__half_as_ushort(lo) | ((uint32_t)__half_as_ushort(hi) << 16);
}

// ---------------- split fp32 -> fp16 hi/lo (4 elems per thread) ----------------
// sel 0: src=x       -> g_xhi/g_xlo   (+ zero g_hsum16/g_fcsum)
// sel 1: src=h_child -> g_hhi/g_hlo
__global__ void k_split(const float* __restrict__ src, int sel) {
    const int total4 = NN * HS / 4;
    int i = blockIdx.x * blockDim.x + threadIdx.x;
    if (i >= total4) return;
    __half* hi = (sel == 0) ? g_xhi : g_hhi;
    __half* lo = (sel == 0) ? g_xlo : g_hlo;
    if (sel == 0) {
        reinterpret_cast<float4*>(g_fcsum)[i] = make_float4(0.f, 0.f, 0.f, 0.f);
        reinterpret_cast<uint2*>(g_hsum16)[i] = make_uint2(0u, 0u);   // 4 halfs
    }
    float4 v = reinterpret_cast<const float4*>(src)[i];
    float f[4] = {v.x, v.y, v.z, v.w};
    uint32_t hp[2], lp[2];
#pragma unroll
    for (int p = 0; p < 2; p++) {
        __half h0 = __float2half_rn(f[2 * p]);
        __half h1 = __float2half_rn(f[2 * p + 1]);
        __half l0 = __float2half_rn(f[2 * p] - __half2float(h0));
        __half l1 = __float2half_rn(f[2 * p + 1] - __half2float(h1));
        hp[p] = pack2h(h0, h1);
        lp[p] = pack2h(l0, l1);
    }
    reinterpret_cast<uint2*>(hi)[i] = make_uint2(hp[0], hp[1]);
    reinterpret_cast<uint2*>(lo)[i] = make_uint2(lp[0], lp[1]);
}

// ---------------- pack weights: fp32 -> fp16, row-major [n][k] tiles ----------------
__global__ void k_prep(const float* __restrict__ w_iou, const float* __restrict__ w_f,
                       const float* __restrict__ u_iou, const float* __restrict__ u_f,
                       const float* __restrict__ b_iou, const float* __restrict__ b_f) {
    int i = blockIdx.x * blockDim.x + threadIdx.x;
    if (i < 512) g_bias[i] = (i < 384) ? b_iou[i] : b_f[i - 384];
    if (i >= 131072) return;
    int n, k, tile;
    float val;
    if (i < 65536) {                       // [w_iou ; w_f], 512 rows
        n = i >> 7; k = i & 127;
        tile = n >> 7;
        val = (n < 384) ? w_iou[n * 128 + k] : w_f[(n - 384) * 128 + k];
    } else if (i < 65536 + 49152) {        // u_iou, 384 rows
        int j = i - 65536;
        n = j >> 7; k = j & 127;
        tile = 4 + (n >> 7);
        val = u_iou[n * 128 + k];
    } else {                               // u_f, 128 rows
        int j = i - 114688;
        n = j >> 7; k = j & 127;
        tile = 7;
        val = u_f[n * 128 + k];
    }
    g_Bhi[tile * 16384 + (n & 127) * 128 + k] = __float2half_rn(val);
}

// swizzled byte offset of 16B chunk (r, c) in a [128 rows x 16 chunks] tile
__device__ __forceinline__ uint32_t sw_chunk(int r, int c) {
    return (uint32_t)(r * 256 + ((c ^ (r & 7)) << 4));
}

// copy one [128][128] fp16 tile, global row-major -> swizzled smem, via cp.async
__device__ __forceinline__ void copy_tile(uint32_t sdst, const __half* gsrc, int tid) {
#pragma unroll
    for (int it = 0; it < 8; it++) {
        int j = tid + it * 256;        // 2048 16B chunks
        int r = j >> 4, c = j & 15;
        cp16(sdst + sw_chunk(r, c), gsrc + r * 128 + c * 8);
    }
}

// ============================================================================
// fp16 mma.sync GEMM. sel 0/1: 2-term split D = Ahi*B + Alo*B.
// sel 2: SINGLE-term (A = g_hsum16 exact fp16, lo==0).
// Swizzled 32KB tiles; A hi/lo + single B = 96KB -> 2 CTAs/SM.
// 256 threads, warp grid 4x2, warp tile 32x64 (R11-proven core).
// sel 0: x -> g_xall (i,o,u fp32, +bias) + g_xf16 (f, fp16, +bias)
// sel 1: h_child -> g_hu16 (fp16)
// sel 2: g_hsum16 -> g_uhsum (fp32, 3 tiles)
// ============================================================================
__global__ void __launch_bounds__(256, 2) k_mma(int sel) {
    const __half* Ahi = (sel == 0) ? g_xhi : (sel == 1) ? g_hhi : g_hsum16;
    const __half* Alo = (sel == 0) ? g_xlo : g_hlo;       // unused for sel 2
    const int first  = (sel == 0) ? 0 : (sel == 1) ? 7 : 4;
    const int ntiles = (sel == 0) ? 4 : (sel == 1) ? 1 : 3;
    const bool twoterm = (sel != 2);

    extern __shared__ __half sm[];
    const int tid = threadIdx.x;
    const int lane = tid & 31, wid = tid >> 5;
    const int brow = blockIdx.x * 128;

    const uint32_t sA = smem_u32(sm);            // A hi; lo at +TSZ
    const uint32_t sB = sA + 2 * TSZ;            // single B buffer

    copy_tile(sA, Ahi + (size_t)brow * 128, tid);
    if (twoterm) copy_tile(sA + TSZ, Alo + (size_t)brow * 128, tid);
    copy_tile(sB, g_Bhi + (size_t)first * 16384, tid);
    cp_commit();

    // ---- warp tiling: 4x2 warps, each 32 rows x 64 cols ----
    const int wr = wid & 3;
    const int wcol = wid >> 2;
    const int aRow = wr * 32 + (lane & 15);
    const int c0a  = lane >> 4;
    const int rma  = aRow & 7;
    const int gg   = lane >> 3;
    const int bRow = wcol * 64 + (gg >> 1) * 8 + (lane & 7);
    const int c0b  = gg & 1;
    const int rmb  = bRow & 7;

    const uint32_t aBase0 = sA + (uint32_t)aRow * 256;
    const uint32_t aBase1 = aBase0 + 16 * 256;
    const uint32_t bBase  = sB + (uint32_t)bRow * 256;

    for (int t = 0; t < ntiles; t++) {
        cp_wait<0>();
        __syncthreads();

        float acc[2][8][4];
#pragma unroll
        for (int i = 0; i < 2; i++)
#pragma unroll
            for (int j = 0; j < 8; j++)
#pragma unroll
                for (int q = 0; q < 4; q++) acc[i][j][q] = 0.f;

#pragma unroll
        for (int kb = 0; kb < 8; kb++) {
            const uint32_t ca = (uint32_t)(((c0a + 2 * kb) ^ rma) << 4);
            const uint32_t cb = (uint32_t)(((c0b + 2 * kb) ^ rmb) << 4);
            uint32_t aH[2][4], aL[2][4];
            ldsm4(aH[0], aBase0 + ca);
            ldsm4(aH[1], aBase1 + ca);
            if (twoterm) {
                ldsm4(aL[0], aBase0 + TSZ + ca);
                ldsm4(aL[1], aBase1 + TSZ + ca);
            }
            uint32_t b[4][4];
#pragma unroll
            for (int p = 0; p < 4; p++)
                ldsm4(b[p], bBase + p * 16 * 256 + cb);
#pragma unroll
            for (int i = 0; i < 2; i++)
#pragma unroll
                for (int j = 0; j < 8; j++) {
                    uint32_t b0 = b[j >> 1][(j & 1) * 2], b1 = b[j >> 1][(j & 1) * 2 + 1];
                    mma16816(acc[i][j], aH[i], b0, b1);
                    if (twoterm) mma16816(acc[i][j], aL[i], b0, b1);
                }
        }

        __syncthreads();
        if (t + 1 < ntiles) {                  // overlap next-B load with epilogue
            copy_tile(sB, g_Bhi + (size_t)(first + t + 1) * 16384, tid);
            cp_commit();
        }

        // ---- epilogue for this column tile ----
        const bool ftile = (sel == 0) && (t == 3);
        const int colb = ((sel == 0 && t < 3) || sel == 2) ? (t * 128 + wcol * 64)
                                                           : (wcol * 64);
        const int biasb = (sel == 0) ? (((t < 3) ? t * 128 : 384) + wcol * 64) : 0;
#pragma unroll
        for (int i = 0; i < 2; i++) {
            int row0 = brow + wr * 32 + i * 16 + (lane >> 2);
            int row1 = row0 + 8;
#pragma unroll
            for (int j = 0; j < 8; j++) {
                int cj = j * 8 + (lane & 3) * 2;
                float bx = 0.f, by = 0.f;
                if (sel == 0) { bx = g_bias[biasb + cj]; by = g_bias[biasb + cj + 1]; }
#pragma unroll
                for (int h2 = 0; h2 < 2; h2++) {
                    int grow = h2 ? row1 : row0;
                    if (grow >= NN) continue;
                    float v0 = acc[i][j][h2 * 2] + bx;
                    float v1 = acc[i][j][h2 * 2 + 1] + by;
                    if (sel == 1) {
                        *reinterpret_cast<__half2*>(g_hu16 + (size_t)grow * HS + colb + cj) =
                            __floats2half2_rn(v0, v1);
                    } else if (ftile) {
                        *reinterpret_cast<__half2*>(g_xf16 + (size_t)grow * HS + (wcol * 64) + cj) =
                            __floats2half2_rn(v0, v1);
                    } else if (sel == 0) {
                        *reinterpret_cast<float2*>(g_xall + (size_t)grow * 384 + colb + cj) =
                            make_float2(v0, v1);
                    } else {
                        *reinterpret_cast<float2*>(g_uhsum + (size_t)grow * 384 + colb + cj) =
                            make_float2(v0, v1);
                    }
                }
            }
        }
    }
}

// ---------------- edge pass: one warp per edge; half2 atomics for hsum ----------------
__global__ void k_edge(const float* __restrict__ h_child, const float* __restrict__ c_child,
                       const int* __restrict__ esrc, const int* __restrict__ edst) {
    int idx = blockIdx.x * blockDim.x + threadIdx.x;
    int e = idx >> 5;
    int q = idx & 31;
    if (e >= NE) return;
    int s = esrc[e];
    int d = edst[e];
    float4 h4 = reinterpret_cast<const float4*>(h_child + (size_t)s * HS)[q];
    float4 c4 = reinterpret_cast<const float4*>(c_child + (size_t)s * HS)[q];
    const __half2* hu2 = reinterpret_cast<const __half2*>(g_hu16 + (size_t)s * HS + q * 4);
    const __half2* xf2 = reinterpret_cast<const __half2*>(g_xf16 + (size_t)d * HS + q * 4);
    float2 huA = __half22float2(hu2[0]), huB = __half22float2(hu2[1]);
    float2 xfA = __half22float2(xf2[0]), xfB = __half22float2(xf2[1]);
    __half2* hs = reinterpret_cast<__half2*>(g_hsum16 + (size_t)d * HS + q * 4);
    float* fc = g_fcsum + (size_t)d * HS + q * 4;
    atomicAdd(hs,     __floats2half2_rn(h4.x, h4.y));
    atomicAdd(hs + 1, __floats2half2_rn(h4.z, h4.w));
    atomicAdd(fc + 0, sigmoidf(xfA.x + huA.x) * c4.x);
    atomicAdd(fc + 1, sigmoidf(xfA.y + huA.y) * c4.y);
    atomicAdd(fc + 2, sigmoidf(xfB.x + huB.x) * c4.z);
    atomicAdd(fc + 3, sigmoidf(xfB.y + huB.y) * c4.w);
}

// ---------------- final node update (streaming, high occupancy) ----------------
__global__ void k_final(float* __restrict__ out) {
    int idx = blockIdx.x * blockDim.x + threadIdx.x;
    if (idx >= NN * HS) return;
    int n = idx >> 7;
    int j = idx & 127;
    size_t b = (size_t)n * 384;
    float i_ = sigmoidf(g_xall[b + j]       + g_uhsum[b + j]);
    float o_ = sigmoidf(g_xall[b + 128 + j] + g_uhsum[b + 128 + j]);
    float u_ = tanhf(   g_xall[b + 256 + j] + g_uhsum[b + 256 + j]);
    float c = i_ * u_ + g_fcsum[idx];
    float h = o_ * tanhf(c);
    out[idx] = h;
    out[(size_t)NN * HS + idx] = c;
}

// ============================================================================
extern "C" void kernel_launch(void* const* d_in, const int* in_sizes, int n_in,
                              void* d_out, int out_size) {
    const float* x       = (const float*)d_in[0];
    const float* h_child = (const float*)d_in[1];
    const float* c_child = (const float*)d_in[2];
    const float* w_iou   = (const float*)d_in[3];
    const float* b_iou   = (const float*)d_in[4];
    const float* w_f     = (const float*)d_in[5];
    const float* b_f     = (const float*)d_in[6];
    const float* u_iou   = (const float*)d_in[7];
    const float* u_f     = (const float*)d_in[8];
    const int*   esrc    = (const int*)d_in[9];
    const int*   edst    = (const int*)d_in[10];
    float* out = (float*)d_out;

    static bool configured = false;
    if (!configured) {
        cudaFuncSetAttribute(k_mma, cudaFuncAttributeMaxDynamicSharedMemorySize, SMEM_MMA);
        configured = true;
    }

    const int total4 = NN * HS / 4;
    const int sgrid = (total4 + 255) / 256;

    k_prep<<<131072 / 256, 256>>>(w_iou, w_f, u_iou, u_f, b_iou, b_f);
    k_split<<<sgrid, 256>>>(x, 0);            // also zeroes g_hsum16/g_fcsum
    k_split<<<sgrid, 256>>>(h_child, 1);
    k_mma<<<ROW_TILES, 256, SMEM_MMA>>>(0);   // x -> g_xall (i|o|u) + g_xf16 (f)
    k_mma<<<ROW_TILES, 256, SMEM_MMA>>>(1);   // h_child -> g_hu16
    k_edge<<<(NE * 32) / 256, 256>>>(h_child, c_child, esrc, edst);
    k_mma<<<ROW_TILES, 256, SMEM_MMA>>>(2);   // g_hsum16 -> g_uhsum (single-term)
    k_final<<<(NN * HS + 255) / 256, 256>>>(out);
}

// round 16
// speedup vs baseline: 1.5595x; 1.2547x over previous
#include <cuda_runtime.h>
#include <cuda_fp16.h>
#include <cstdint>

#define NN 200000
#define NE 400000
#define HS 128
#define ROW_TILES 1563            // ceil(200000/128)
#define NPAD (ROW_TILES * 128)    // 200064 padded rows

#define TSZ 32768                 // bytes per swizzled [128x128] fp16 tile
#define SMEM_MMA (3 * TSZ)        // A hi/lo + B single buffer = 98304 B

// ---------------- scratch (device globals; no allocs allowed) ----------------
// NOTE: never passed as kernel args from host (host shadow + ATS trap);
// all resolution happens inside device code.
__device__ float g_xall[(size_t)NN * 384];   // x@w_iou^T + b_iou   [N,384] = i|o|u (fp32)
__device__ __align__(16) __half g_uh16[(size_t)NPAD * 384]; // hsum @ u_iou^T (fp16)
__device__ __align__(16) __half g_xf16[(size_t)NPAD * HS];  // x@w_f^T + b_f (fp16)
__device__ __align__(16) __half g_hu16[(size_t)NPAD * HS];  // h_child @ u_f^T (fp16)
// hsum accumulated DIRECTLY in fp16 (half2 atomics); also the sel2 GEMM A
// operand (exact fp16 -> single-term MMA, no lo tile).
__device__ __align__(16) __half g_hsum16[(size_t)NPAD * HS];
__device__ float g_fcsum[(size_t)NN * HS];   // segsum(f*c_child[src])  [N,128] (fp32)
// pre-split fp16 A operands: A = hi + lo (22-bit effective mantissa)
__device__ __align__(16) __half g_xhi[(size_t)NPAD * HS];
__device__ __align__(16) __half g_xlo[(size_t)NPAD * HS];
__device__ __align__(16) __half g_hhi[(size_t)NPAD * HS];
__device__ __align__(16) __half g_hlo[(size_t)NPAD * HS];
// packed fp16 weights (hi only), 8 tiles of [128 n][128 k] row-major:
// tiles 0-3: [w_iou;w_f] (512 rows: 0=i,1=o,2=u,3=f), 4-6: u_iou (4=i,5=o,6=u), 7: u_f
__device__ __align__(16) __half g_Bhi[8 * 16384];
__device__ __align__(16) float g_bias[512];

__device__ __forceinline__ float sigmoidf(float v) { return 1.0f / (1.0f + __expf(-v)); }

__device__ __forceinline__ uint32_t smem_u32(const void* p) {
    uint32_t a;
    asm("{ .reg .u64 t; cvta.to.shared.u64 t, %1; cvt.u32.u64 %0, t; }" : "=r"(a) : "l"(p));
    return a;
}

__device__ __forceinline__ void ldsm4(uint32_t* r, uint32_t addr) {
    asm volatile("ldmatrix.sync.aligned.m8n8.x4.shared.b16 {%0,%1,%2,%3}, [%4];"
                 : "=r"(r[0]), "=r"(r[1]), "=r"(r[2]), "=r"(r[3]) : "r"(addr));
}

__device__ __forceinline__ void mma16816(float* c, const uint32_t* a, uint32_t b0, uint32_t b1) {
    asm volatile(
        "mma.sync.aligned.m16n8k16.row.col.f32.f16.f16.f32 "
        "{%0,%1,%2,%3}, {%4,%5,%6,%7}, {%8,%9}, {%0,%1,%2,%3};"
        : "+f"(c[0]), "+f"(c[1]), "+f"(c[2]), "+f"(c[3])
        : "r"(a[0]), "r"(a[1]), "r"(a[2]), "r"(a[3]), "r"(b0), "r"(b1));
}

__device__ __forceinline__ void cp16(uint32_t dst, const void* src) {
    asm volatile("cp.async.cg.shared.global [%0], [%1], 16;" :: "r"(dst), "l"(src));
}
__device__ __forceinline__ void cp_commit() {
    asm volatile("cp.async.commit_group;");
}
template <int N>
__device__ __forceinline__ void cp_wait() {
    asm volatile("cp.async.wait_group %0;" :: "n"(N));
}

__device__ __forceinline__ uint32_t pack2h(__half lo, __half hi) {
    return (uint32_t)__half_as_ushort(lo) | ((uint32_t)__half_as_ushort(hi) << 16);
}

// ---------------- split fp32 -> fp16 hi/lo (4 elems per thread) ----------------
// sel 0: src=x       -> g_xhi/g_xlo   (+ zero g_hsum16/g_fcsum)
// sel 1: src=h_child -> g_hhi/g_hlo
__global__ void k_split(const float* __restrict__ src, int sel) {
    const int total4 = NN * HS / 4;
    int i = blockIdx.x * blockDim.x + threadIdx.x;
    if (i >= total4) return;
    __half* hi = (sel == 0) ? g_xhi : g_hhi;
    __half* lo = (sel == 0) ? g_xlo : g_hlo;
    if (sel == 0) {
        reinterpret_cast<float4*>(g_fcsum)[i] = make_float4(0.f, 0.f, 0.f, 0.f);
        reinterpret_cast<uint2*>(g_hsum16)[i] = make_uint2(0u, 0u);   // 4 halfs
    }
    float4 v = reinterpret_cast<const float4*>(src)[i];
    float f[4] = {v.x, v.y, v.z, v.w};
    uint32_t hp[2], lp[2];
#pragma unroll
    for (int p = 0; p < 2; p++) {
        __half h0 = __float2half_rn(f[2 * p]);
        __half h1 = __float2half_rn(f[2 * p + 1]);
        __half l0 = __float2half_rn(f[2 * p] - __half2float(h0));
        __half l1 = __float2half_rn(f[2 * p + 1] - __half2float(h1));
        hp[p] = pack2h(h0, h1);
        lp[p] = pack2h(l0, l1);
    }
    reinterpret_cast<uint2*>(hi)[i] = make_uint2(hp[0], hp[1]);
    reinterpret_cast<uint2*>(lo)[i] = make_uint2(lp[0], lp[1]);
}

// ---------------- pack weights: fp32 -> fp16, row-major [n][k] tiles ----------------
__global__ void k_prep(const float* __restrict__ w_iou, const float* __restrict__ w_f,
                       const float* __restrict__ u_iou, const float* __restrict__ u_f,
                       const float* __restrict__ b_iou, const float* __restrict__ b_f) {
    int i = blockIdx.x * blockDim.x + threadIdx.x;
    if (i < 512) g_bias[i] = (i < 384) ? b_iou[i] : b_f[i - 384];
    if (i >= 131072) return;
    int n, k, tile;
    float val;
    if (i < 65536) {                       // [w_iou ; w_f], 512 rows
        n = i >> 7; k = i & 127;
        tile = n >> 7;
        val = (n < 384) ? w_iou[n * 128 + k] : w_f[(n - 384) * 128 + k];
    } else if (i < 65536 + 49152) {        // u_iou, 384 rows
        int j = i - 65536;
        n = j >> 7; k = j & 127;
        tile = 4 + (n >> 7);
        val = u_iou[n * 128 + k];
    } else {                               // u_f, 128 rows
        int j = i - 114688;
        n = j >> 7; k = j & 127;
        tile = 7;
        val = u_f[n * 128 + k];
    }
    g_Bhi[tile * 16384 + (n & 127) * 128 + k] = __float2half_rn(val);
}

// swizzled byte offset of 16B chunk (r, c) in a [128 rows x 16 chunks] tile
__device__ __forceinline__ uint32_t sw_chunk(int r, int c) {
    return (uint32_t)(r * 256 + ((c ^ (r & 7)) << 4));
}

// copy one [128][128] fp16 tile, global row-major -> swizzled smem, via cp.async
__device__ __forceinline__ void copy_tile(uint32_t sdst, const __half* gsrc, int tid) {
#pragma unroll
    for (int it = 0; it < 8; it++) {
        int j = tid + it * 256;        // 2048 16B chunks
        int r = j >> 4, c = j & 15;
        cp16(sdst + sw_chunk(r, c), gsrc + r * 128 + c * 8);
    }
}

// ============================================================================
// fp16 mma.sync GEMM, template-specialized per SEL (compile-time bases, no
// runtime branches in the hot loop).
// SEL 0: 2-term, x -> g_xall (i,o,u fp32, +bias) + g_xf16 (f, fp16, +bias)
// SEL 1: 2-term, h_child -> g_hu16 (fp16)
// SEL 2: 1-term (A = g_hsum16 exact fp16), -> g_uh16 (fp16, 3 tiles)
// Swizzled 32KB tiles; 96KB smem -> 2 CTAs/SM. 256 thr, 4x2 warps, 32x64 tile.
// ============================================================================
template <int SEL>
__global__ void __launch_bounds__(256, 2) k_mma() {
    const __half* Ahi = (SEL == 0) ? g_xhi : (SEL == 1) ? g_hhi : g_hsum16;
    const __half* Alo = (SEL == 0) ? g_xlo : g_hlo;       // unused for SEL 2
    constexpr int first  = (SEL == 0) ? 0 : (SEL == 1) ? 7 : 4;
    constexpr int ntiles = (SEL == 0) ? 4 : (SEL == 1) ? 1 : 3;
    constexpr bool twoterm = (SEL != 2);

    extern __shared__ __half sm[];
    const int tid = threadIdx.x;
    const int lane = tid & 31, wid = tid >> 5;
    const int brow = blockIdx.x * 128;

    const uint32_t sA = smem_u32(sm);            // A hi; lo at +TSZ
    const uint32_t sB = sA + 2 * TSZ;            // single B buffer

    copy_tile(sA, Ahi + (size_t)brow * 128, tid);
    if (twoterm) copy_tile(sA + TSZ, Alo + (size_t)brow * 128, tid);
    copy_tile(sB, g_Bhi + (size_t)first * 16384, tid);
    cp_commit();

    // ---- warp tiling: 4x2 warps, each 32 rows x 64 cols ----
    const int wr = wid & 3;
    const int wcol = wid >> 2;
    const int aRow = wr * 32 + (lane & 15);
    const int c0a  = lane >> 4;
    const int rma  = aRow & 7;
    const int gg   = lane >> 3;
    const int bRow = wcol * 64 + (gg >> 1) * 8 + (lane & 7);
    const int c0b  = gg & 1;
    const int rmb  = bRow & 7;

    const uint32_t aBase0 = sA + (uint32_t)aRow * 256;
    const uint32_t aBase1 = aBase0 + 16 * 256;
    const uint32_t bBase  = sB + (uint32_t)bRow * 256;

#pragma unroll 1
    for (int t = 0; t < ntiles; t++) {
        cp_wait<0>();
        __syncthreads();

        float acc[2][8][4];
#pragma unroll
        for (int i = 0; i < 2; i++)
#pragma unroll
            for (int j = 0; j < 8; j++)
#pragma unroll
                for (int q = 0; q < 4; q++) acc[i][j][q] = 0.f;

#pragma unroll
        for (int kb = 0; kb < 8; kb++) {
            const uint32_t ca = (uint32_t)(((c0a + 2 * kb) ^ rma) << 4);
            const uint32_t cb = (uint32_t)(((c0b + 2 * kb) ^ rmb) << 4);
            uint32_t aH[2][4], aL[2][4];
            ldsm4(aH[0], aBase0 + ca);
            ldsm4(aH[1], aBase1 + ca);
            if (twoterm) {
                ldsm4(aL[0], aBase0 + TSZ + ca);
                ldsm4(aL[1], aBase1 + TSZ + ca);
            }
            uint32_t b[4][4];
#pragma unroll
            for (int p = 0; p < 4; p++)
                ldsm4(b[p], bBase + p * 16 * 256 + cb);
#pragma unroll
            for (int i = 0; i < 2; i++)
#pragma unroll
                for (int j = 0; j < 8; j++) {
                    uint32_t b0 = b[j >> 1][(j & 1) * 2], b1 = b[j >> 1][(j & 1) * 2 + 1];
                    mma16816(acc[i][j], aH[i], b0, b1);
                    if (twoterm) mma16816(acc[i][j], aL[i], b0, b1);
                }
        }

        __syncthreads();
        if (t + 1 < ntiles) {                  // overlap next-B load with epilogue
            copy_tile(sB, g_Bhi + (size_t)(first + t + 1) * 16384, tid);
            cp_commit();
        }

        // ---- epilogue for this column tile ----
        const bool ftile = (SEL == 0) && (t == 3);
        const int colb = ((SEL == 0 && t < 3) || SEL == 2) ? (t * 128 + wcol * 64)
                                                           : (wcol * 64);
        const int biasb = (SEL == 0) ? (((t < 3) ? t * 128 : 384) + wcol * 64) : 0;
#pragma unroll
        for (int i = 0; i < 2; i++) {
            int row0 = brow + wr * 32 + i * 16 + (lane >> 2);
            int row1 = row0 + 8;
#pragma unroll
            for (int j = 0; j < 8; j++) {
                int cj = j * 8 + (lane & 3) * 2;
                float bx = 0.f, by = 0.f;
                if (SEL == 0) { bx = g_bias[biasb + cj]; by = g_bias[biasb + cj + 1]; }
#pragma unroll
                for (int h2 = 0; h2 < 2; h2++) {
                    int grow = h2 ? row1 : row0;
                    if (grow >= NN) continue;
                    float v0 = acc[i][j][h2 * 2] + bx;
                    float v1 = acc[i][j][h2 * 2 + 1] + by;
                    if (SEL == 1) {
                        *reinterpret_cast<__half2*>(g_hu16 + (size_t)grow * HS + colb + cj) =
                            __floats2half2_rn(v0, v1);
                    } else if (SEL == 0 && ftile) {
                        *reinterpret_cast<__half2*>(g_xf16 + (size_t)grow * HS + (wcol * 64) + cj) =
                            __floats2half2_rn(v0, v1);
                    } else if (SEL == 0) {
                        *reinterpret_cast<float2*>(g_xall + (size_t)grow * 384 + colb + cj) =
                            make_float2(v0, v1);
                    } else {
                        *reinterpret_cast<__half2*>(g_uh16 + (size_t)grow * 384 + colb + cj) =
                            __floats2half2_rn(v0, v1);
                    }
                }
            }
        }
    }
}

// ---------------- edge pass: one warp per edge; half2 atomics for hsum ----------------
__global__ void k_edge(const float* __restrict__ h_child, const float* __restrict__ c_child,
                       const int* __restrict__ esrc, const int* __restrict__ edst) {
    int idx = blockIdx.x * blockDim.x + threadIdx.x;
    int e = idx >> 5;
    int q = idx & 31;
    if (e >= NE) return;
    int s = esrc[e];
    int d = edst[e];
    float4 h4 = reinterpret_cast<const float4*>(h_child + (size_t)s * HS)[q];
    float4 c4 = reinterpret_cast<const float4*>(c_child + (size_t)s * HS)[q];
    const __half2* hu2 = reinterpret_cast<const __half2*>(g_hu16 + (size_t)s * HS + q * 4);
    const __half2* xf2 = reinterpret_cast<const __half2*>(g_xf16 + (size_t)d * HS + q * 4);
    float2 huA = __half22float2(hu2[0]), huB = __half22float2(hu2[1]);
    float2 xfA = __half22float2(xf2[0]), xfB = __half22float2(xf2[1]);
    __half2* hs = reinterpret_cast<__half2*>(g_hsum16 + (size_t)d * HS + q * 4);
    float* fc = g_fcsum + (size_t)d * HS + q * 4;
    atomicAdd(hs,     __floats2half2_rn(h4.x, h4.y));
    atomicAdd(hs + 1, __floats2half2_rn(h4.z, h4.w));
    atomicAdd(fc + 0, sigmoidf(xfA.x + huA.x) * c4.x);
    atomicAdd(fc + 1, sigmoidf(xfA.y + huA.y) * c4.y);
    atomicAdd(fc + 2, sigmoidf(xfB.x + huB.x) * c4.z);
    atomicAdd(fc + 3, sigmoidf(xfB.y + huB.y) * c4.w);
}

// ---------------- final node update (streaming; 2 elems/thread) ----------------
__global__ void k_final(float* __restrict__ out) {
    int idx = blockIdx.x * blockDim.x + threadIdx.x;   // over NN*64
    if (idx >= NN * 64) return;
    int n = idx >> 6;
    int cj = (idx & 63) * 2;
    const float*  xr = g_xall + (size_t)n * 384;
    const __half* ur = g_uh16 + (size_t)n * 384;
    float2 xi = *reinterpret_cast<const float2*>(xr + cj);
    float2 xo = *reinterpret_cast<const float2*>(xr + 128 + cj);
    float2 xu = *reinterpret_cast<const float2*>(xr + 256 + cj);
    float2 ui = __half22float2(*reinterpret_cast<const __half2*>(ur + cj));
    float2 uo = __half22float2(*reinterpret_cast<const __half2*>(ur + 128 + cj));
    float2 uu = __half22float2(*reinterpret_cast<const __half2*>(ur + 256 + cj));
    float2 fc = *reinterpret_cast<const float2*>(g_fcsum + (size_t)n * HS + cj);
    float c0 = sigmoidf(xi.x + ui.x) * tanhf(xu.x + uu.x) + fc.x;
    float c1 = sigmoidf(xi.y + ui.y) * tanhf(xu.y + uu.y) + fc.y;
    float h0 = sigmoidf(xo.x + uo.x) * tanhf(c0);
    float h1 = sigmoidf(xo.y + uo.y) * tanhf(c1);
    *reinterpret_cast<float2*>(out + (size_t)n * HS + cj) = make_float2(h0, h1);
    *reinterpret_cast<float2*>(out + (size_t)NN * HS + (size_t)n * HS + cj) =
        make_float2(c0, c1);
}

// ============================================================================
extern "C" void kernel_launch(void* const* d_in, const int* in_sizes, int n_in,
                              void* d_out, int out_size) {
    const float* x       = (const float*)d_in[0];
    const float* h_child = (const float*)d_in[1];
    const float* c_child = (const float*)d_in[2];
    const float* w_iou   = (const float*)d_in[3];
    const float* b_iou   = (const float*)d_in[4];
    const float* w_f     = (const float*)d_in[5];
    const float* b_f     = (const float*)d_in[6];
    const float* u_iou   = (const float*)d_in[7];
    const float* u_f     = (const float*)d_in[8];
    const int*   esrc    = (const int*)d_in[9];
    const int*   edst    = (const int*)d_in[10];
    float* out = (float*)d_out;

    static bool configured = false;
    if (!configured) {
        cudaFuncSetAttribute(k_mma<0>, cudaFuncAttributeMaxDynamicSharedMemorySize, SMEM_MMA);
        cudaFuncSetAttribute(k_mma<1>, cudaFuncAttributeMaxDynamicSharedMemorySize, SMEM_MMA);
        cudaFuncSetAttribute(k_mma<2>, cudaFuncAttributeMaxDynamicSharedMemorySize, SMEM_MMA);
        configured = true;
    }

    const int total4 = NN * HS / 4;
    const int sgrid = (total4 + 255) / 256;

    k_prep<<<131072 / 256, 256>>>(w_iou, w_f, u_iou, u_f, b_iou, b_f);
    k_split<<<sgrid, 256>>>(x, 0);              // also zeroes g_hsum16/g_fcsum
    k_split<<<sgrid, 256>>>(h_child, 1);
    k_mma<0><<<ROW_TILES, 256, SMEM_MMA>>>();   // x -> g_xall (i|o|u) + g_xf16 (f)
    k_mma<1><<<ROW_TILES, 256, SMEM_MMA>>>();   // h_child -> g_hu16
    k_edge<<<(NE * 32) / 256, 256>>>(h_child, c_child, esrc, edst);
    k_mma<2><<<ROW_TILES, 256, SMEM_MMA>>>();   // g_hsum16 -> g_uh16 (single-term)
    k_final<<<(NN * 64 + 255) / 256, 256>>>(out);
}

// round 17
// speedup vs baseline: 1.6379x; 1.0503x over previous
#include <cuda_runtime.h>
#include <cuda_fp16.h>
#include <cstdint>

#define NN 200000
#define NE 400000
#define HS 128
#define ROW_TILES 1563            // ceil(200000/128)
#define NPAD (ROW_TILES * 128)    // 200064 padded rows

#define TSZ 32768                 // bytes per swizzled [128x128] fp16 tile
#define SMEM_MMA (3 * TSZ)        // A hi/lo + B single buffer = 98304 B

// ---------------- scratch (device globals; no allocs allowed) ----------------
// NOTE: never passed as kernel args from host (host shadow + ATS trap);
// all resolution happens inside device code.
__device__ __align__(16) __half g_xa16[(size_t)NPAD * 384]; // x@w_iou^T + b_iou (fp16)
__device__ __align__(16) __half g_uh16[(size_t)NPAD * 384]; // hsum @ u_iou^T (fp16)
__device__ __align__(16) __half g_xf16[(size_t)NPAD * HS];  // x@w_f^T + b_f (fp16)
__device__ __align__(16) __half g_hu16[(size_t)NPAD * HS];  // h_child @ u_f^T (fp16)
// hsum accumulated DIRECTLY in fp16 (half2 atomics); also the sel2 GEMM A
// operand (exact fp16 -> single-term MMA, no lo tile).
__device__ __align__(16) __half g_hsum16[(size_t)NPAD * HS];
__device__ float g_fcsum[(size_t)NN * HS];   // segsum(f*c_child[src])  [N,128] (fp32)
// packed fp16 weights (hi only), 8 tiles of [128 n][128 k] row-major:
// tiles 0-3: [w_iou;w_f] (512 rows: 0=i,1=o,2=u,3=f), 4-6: u_iou (4=i,5=o,6=u), 7: u_f
__device__ __align__(16) __half g_Bhi[8 * 16384];
__device__ __align__(16) float g_bias[512];

__device__ __forceinline__ float sigmoidf(float v) { return 1.0f / (1.0f + __expf(-v)); }

__device__ __forceinline__ uint32_t smem_u32(const void* p) {
    uint32_t a;
    asm("{ .reg .u64 t; cvta.to.shared.u64 t, %1; cvt.u32.u64 %0, t; }" : "=r"(a) : "l"(p));
    return a;
}

__device__ __forceinline__ void ldsm4(uint32_t* r, uint32_t addr) {
    asm volatile("ldmatrix.sync.aligned.m8n8.x4.shared.b16 {%0,%1,%2,%3}, [%4];"
                 : "=r"(r[0]), "=r"(r[1]), "=r"(r[2]), "=r"(r[3]) : "r"(addr));
}

__device__ __forceinline__ void mma16816(float* c, const uint32_t* a, uint32_t b0, uint32_t b1) {
    asm volatile(
        "mma.sync.aligned.m16n8k16.row.col.f32.f16.f16.f32 "
        "{%0,%1,%2,%3}, {%4,%5,%6,%7}, {%8,%9}, {%0,%1,%2,%3};"
        : "+f"(c[0]), "+f"(c[1]), "+f"(c[2]), "+f"(c[3])
        : "r"(a[0]), "r"(a[1]), "r"(a[2]), "r"(a[3]), "r"(b0), "r"(b1));
}

__device__ __forceinline__ void cp16(uint32_t dst, const void* src) {
    asm volatile("cp.async.cg.shared.global [%0], [%1], 16;" :: "r"(dst), "l"(src));
}
__device__ __forceinline__ void cp_commit() {
    asm volatile("cp.async.commit_group;");
}
template <int N>
__device__ __forceinline__ void cp_wait() {
    asm volatile("cp.async.wait_group %0;" :: "n"(N));
}

__device__ __forceinline__ uint32_t pack2h(__half lo, __half hi) {
    return (uint32_t)__half_as_ushort(lo) | ((uint32_t)__half_as_ushort(hi) << 16);
}

// ---------------- zero accumulators ----------------
__global__ void k_zero() {
    const int total4 = NN * HS / 4;
    int i = blockIdx.x * blockDim.x + threadIdx.x;
    if (i >= total4) return;
    reinterpret_cast<float4*>(g_fcsum)[i] = make_float4(0.f, 0.f, 0.f, 0.f);
    reinterpret_cast<uint2*>(g_hsum16)[i] = make_uint2(0u, 0u);   // 4 halfs
}

// ---------------- pack weights: fp32 -> fp16, row-major [n][k] tiles ----------------
__global__ void k_prep(const float* __restrict__ w_iou, const float* __restrict__ w_f,
                       const float* __restrict__ u_iou, const float* __restrict__ u_f,
                       const float* __restrict__ b_iou, const float* __restrict__ b_f) {
    int i = blockIdx.x * blockDim.x + threadIdx.x;
    if (i < 512) g_bias[i] = (i < 384) ? b_iou[i] : b_f[i - 384];
    if (i >= 131072) return;
    int n, k, tile;
    float val;
    if (i < 65536) {                       // [w_iou ; w_f], 512 rows
        n = i >> 7; k = i & 127;
        tile = n >> 7;
        val = (n < 384) ? w_iou[n * 128 + k] : w_f[(n - 384) * 128 + k];
    } else if (i < 65536 + 49152) {        // u_iou, 384 rows
        int j = i - 65536;
        n = j >> 7; k = j & 127;
        tile = 4 + (n >> 7);
        val = u_iou[n * 128 + k];
    } else {                               // u_f, 128 rows
        int j = i - 114688;
        n = j >> 7; k = j & 127;
        tile = 7;
        val = u_f[n * 128 + k];
    }
    g_Bhi[tile * 16384 + (n & 127) * 128 + k] = __float2half_rn(val);
}

// swizzled byte offset of 16B chunk (r, c) in a [128 rows x 16 chunks] tile
__device__ __forceinline__ uint32_t sw_chunk(int r, int c) {
    return (uint32_t)(r * 256 + ((c ^ (r & 7)) << 4));
}

// copy one [128][128] fp16 tile, global row-major -> swizzled smem, via cp.async
__device__ __forceinline__ void copy_tile(uint32_t sdst, const __half* gsrc, int tid) {
#pragma unroll
    for (int it = 0; it < 8; it++) {
        int j = tid + it * 256;        // 2048 16B chunks
        int r = j >> 4, c = j & 15;
        cp16(sdst + sw_chunk(r, c), gsrc + r * 128 + c * 8);
    }
}

// ============================================================================
// fp16 mma.sync GEMM, template-specialized per SEL.
// SEL 0: 2-term, A = x (fp32, split hi/lo IN PROLOGUE) -> g_xa16 + g_xf16, +bias
// SEL 1: 2-term, A = h_child (fp32, split in prologue) -> g_hu16
// SEL 2: 1-term, A = g_hsum16 (exact fp16, cp.async)   -> g_uh16 (3 tiles)
// Swizzled 32KB tiles; 96KB smem -> 2 CTAs/SM. 256 thr, 4x2 warps, 32x64 tile.
// ============================================================================
template <int SEL>
__global__ void __launch_bounds__(256, 2) k_mma(const float* __restrict__ Asrc) {
    constexpr int first  = (SEL == 0) ? 0 : (SEL == 1) ? 7 : 4;
    constexpr int ntiles = (SEL == 0) ? 4 : (SEL == 1) ? 1 : 3;
    constexpr bool twoterm = (SEL != 2);

    extern __shared__ char sm[];
    const int tid = threadIdx.x;
    const int lane = tid & 31, wid = tid >> 5;
    const int brow = blockIdx.x * 128;

    const uint32_t sA = smem_u32(sm);            // A hi; lo at +TSZ
    const uint32_t sB = sA + 2 * TSZ;            // single B buffer

    // B always via cp.async (hides under A conversion / prologue)
    copy_tile(sB, g_Bhi + (size_t)first * 16384, tid);
    cp_commit();

    if (twoterm) {
        // inline split: read A fp32 rows, emit hi/lo fp16 swizzled tiles
        const int row = tid & 127;
        const int kh = tid >> 7;                 // 0 or 1: which 64-col half
        const int grow = brow + row;
        const bool ok = grow < NN;
        const float* ar = Asrc + (size_t)grow * 128 + kh * 64;
#pragma unroll
        for (int c = 0; c < 8; c++) {
            float f[8];
            if (ok) {
                float4 v0 = *reinterpret_cast<const float4*>(ar + c * 8);
                float4 v1 = *reinterpret_cast<const float4*>(ar + c * 8 + 4);
                f[0] = v0.x; f[1] = v0.y; f[2] = v0.z; f[3] = v0.w;
                f[4] = v1.x; f[5] = v1.y; f[6] = v1.z; f[7] = v1.w;
            } else {
#pragma unroll
                for (int p = 0; p < 8; p++) f[p] = 0.f;
            }
            uint32_t hp[4], lp[4];
#pragma unroll
            for (int p = 0; p < 4; p++) {
                __half h0 = __float2half_rn(f[2 * p]);
                __half h1 = __float2half_rn(f[2 * p + 1]);
                __half l0 = __float2half_rn(f[2 * p] - __half2float(h0));
                __half l1 = __float2half_rn(f[2 * p + 1] - __half2float(h1));
                hp[p] = pack2h(h0, h1);
                lp[p] = pack2h(l0, l1);
            }
            uint32_t off = sw_chunk(row, kh * 8 + c);
            *reinterpret_cast<uint4*>(sm + off) = make_uint4(hp[0], hp[1], hp[2], hp[3]);
            *reinterpret_cast<uint4*>(sm + TSZ + off) = make_uint4(lp[0], lp[1], lp[2], lp[3]);
        }
    } else {
        copy_tile(sA, g_hsum16 + (size_t)brow * 128, tid);
        cp_commit();
    }

    // ---- warp tiling: 4x2 warps, each 32 rows x 64 cols ----
    const int wr = wid & 3;
    const int wcol = wid >> 2;
    const int aRow = wr * 32 + (lane & 15);
    const int c0a  = lane >> 4;
    const int rma  = aRow & 7;
    const int gg   = lane >> 3;
    const int bRow = wcol * 64 + (gg >> 1) * 8 + (lane & 7);
    const int c0b  = gg & 1;
    const int rmb  = bRow & 7;

    const uint32_t aBase0 = sA + (uint32_t)aRow * 256;
    const uint32_t aBase1 = aBase0 + 16 * 256;
    const uint32_t bBase  = sB + (uint32_t)bRow * 256;

#pragma unroll 1
    for (int t = 0; t < ntiles; t++) {
        cp_wait<0>();
        __syncthreads();

        float acc[2][8][4];
#pragma unroll
        for (int i = 0; i < 2; i++)
#pragma unroll
            for (int j = 0; j < 8; j++)
#pragma unroll
                for (int q = 0; q < 4; q++) acc[i][j][q] = 0.f;

#pragma unroll
        for (int kb = 0; kb < 8; kb++) {
            const uint32_t ca = (uint32_t)(((c0a + 2 * kb) ^ rma) << 4);
            const uint32_t cb = (uint32_t)(((c0b + 2 * kb) ^ rmb) << 4);
            uint32_t aH[2][4], aL[2][4];
            ldsm4(aH[0], aBase0 + ca);
            ldsm4(aH[1], aBase1 + ca);
            if (twoterm) {
                ldsm4(aL[0], aBase0 + TSZ + ca);
                ldsm4(aL[1], aBase1 + TSZ + ca);
            }
            uint32_t b[4][4];
#pragma unroll
            for (int p = 0; p < 4; p++)
                ldsm4(b[p], bBase + p * 16 * 256 + cb);
#pragma unroll
            for (int i = 0; i < 2; i++)
#pragma unroll
                for (int j = 0; j < 8; j++) {
                    uint32_t b0 = b[j >> 1][(j & 1) * 2], b1 = b[j >> 1][(j & 1) * 2 + 1];
                    mma16816(acc[i][j], aH[i], b0, b1);
                    if (twoterm) mma16816(acc[i][j], aL[i], b0, b1);
                }
        }

        __syncthreads();
        if (t + 1 < ntiles) {                  // overlap next-B load with epilogue
            copy_tile(sB, g_Bhi + (size_t)(first + t + 1) * 16384, tid);
            cp_commit();
        }

        // ---- epilogue for this column tile (all outputs fp16) ----
        const bool ftile = (SEL == 0) && (t == 3);
        const int colb = ((SEL == 0 && t < 3) || SEL == 2) ? (t * 128 + wcol * 64)
                                                           : (wcol * 64);
        const int biasb = (SEL == 0) ? (((t < 3) ? t * 128 : 384) + wcol * 64) : 0;
#pragma unroll
        for (int i = 0; i < 2; i++) {
            int row0 = brow + wr * 32 + i * 16 + (lane >> 2);
            int row1 = row0 + 8;
#pragma unroll
            for (int j = 0; j < 8; j++) {
                int cj = j * 8 + (lane & 3) * 2;
                float bx = 0.f, by = 0.f;
                if (SEL == 0) { bx = g_bias[biasb + cj]; by = g_bias[biasb + cj + 1]; }
#pragma unroll
                for (int h2 = 0; h2 < 2; h2++) {
                    int grow = h2 ? row1 : row0;
                    if (grow >= NN) continue;
                    float v0 = acc[i][j][h2 * 2] + bx;
                    float v1 = acc[i][j][h2 * 2 + 1] + by;
                    __half2 hv = __floats2half2_rn(v0, v1);
                    if (SEL == 1) {
                        *reinterpret_cast<__half2*>(g_hu16 + (size_t)grow * HS + colb + cj) = hv;
                    } else if (SEL == 0 && ftile) {
                        *reinterpret_cast<__half2*>(g_xf16 + (size_t)grow * HS + (wcol * 64) + cj) = hv;
                    } else if (SEL == 0) {
                        *reinterpret_cast<__half2*>(g_xa16 + (size_t)grow * 384 + colb + cj) = hv;
                    } else {
                        *reinterpret_cast<__half2*>(g_uh16 + (size_t)grow * 384 + colb + cj) = hv;
                    }
                }
            }
        }
    }
}

// ---------------- edge pass: one warp per edge; half2 atomics for hsum ----------------
__global__ void k_edge(const float* __restrict__ h_child, const float* __restrict__ c_child,
                       const int* __restrict__ esrc, const int* __restrict__ edst) {
    int idx = blockIdx.x * blockDim.x + threadIdx.x;
    int e = idx >> 5;
    int q = idx & 31;
    if (e >= NE) return;
    int s = esrc[e];
    int d = edst[e];
    float4 h4 = reinterpret_cast<const float4*>(h_child + (size_t)s * HS)[q];
    float4 c4 = reinterpret_cast<const float4*>(c_child + (size_t)s * HS)[q];
    const __half2* hu2 = reinterpret_cast<const __half2*>(g_hu16 + (size_t)s * HS + q * 4);
    const __half2* xf2 = reinterpret_cast<const __half2*>(g_xf16 + (size_t)d * HS + q * 4);
    float2 huA = __half22float2(hu2[0]), huB = __half22float2(hu2[1]);
    float2 xfA = __half22float2(xf2[0]), xfB = __half22float2(xf2[1]);
    __half2* hs = reinterpret_cast<__half2*>(g_hsum16 + (size_t)d * HS + q * 4);
    float* fc = g_fcsum + (size_t)d * HS + q * 4;
    atomicAdd(hs,     __floats2half2_rn(h4.x, h4.y));
    atomicAdd(hs + 1, __floats2half2_rn(h4.z, h4.w));
    atomicAdd(fc + 0, sigmoidf(xfA.x + huA.x) * c4.x);
    atomicAdd(fc + 1, sigmoidf(xfA.y + huA.y) * c4.y);
    atomicAdd(fc + 2, sigmoidf(xfB.x + huB.x) * c4.z);
    atomicAdd(fc + 3, sigmoidf(xfB.y + huB.y) * c4.w);
}

// ---------------- final node update (streaming; 2 elems/thread) ----------------
__global__ void k_final(float* __restrict__ out) {
    int idx = blockIdx.x * blockDim.x + threadIdx.x;   // over NN*64
    if (idx >= NN * 64) return;
    int n = idx >> 6;
    int cj = (idx & 63) * 2;
    const __half* xr = g_xa16 + (size_t)n * 384;
    const __half* ur = g_uh16 + (size_t)n * 384;
    float2 xi = __half22float2(*reinterpret_cast<const __half2*>(xr + cj));
    float2 xo = __half22float2(*reinterpret_cast<const __half2*>(xr + 128 + cj));
    float2 xu = __half22float2(*reinterpret_cast<const __half2*>(xr + 256 + cj));
    float2 ui = __half22float2(*reinterpret_cast<const __half2*>(ur + cj));
    float2 uo = __half22float2(*reinterpret_cast<const __half2*>(ur + 128 + cj));
    float2 uu = __half22float2(*reinterpret_cast<const __half2*>(ur + 256 + cj));
    float2 fc = *reinterpret_cast<const float2*>(g_fcsum + (size_t)n * HS + cj);
    float c0 = sigmoidf(xi.x + ui.x) * tanhf(xu.x + uu.x) + fc.x;
    float c1 = sigmoidf(xi.y + ui.y) * tanhf(xu.y + uu.y) + fc.y;
    float h0 = sigmoidf(xo.x + uo.x) * tanhf(c0);
    float h1 = sigmoidf(xo.y + uo.y) * tanhf(c1);
    *reinterpret_cast<float2*>(out + (size_t)n * HS + cj) = make_float2(h0, h1);
    *reinterpret_cast<float2*>(out + (size_t)NN * HS + (size_t)n * HS + cj) =
        make_float2(c0, c1);
}

// ============================================================================
extern "C" void kernel_launch(void* const* d_in, const int* in_sizes, int n_in,
                              void* d_out, int out_size) {
    const float* x       = (const float*)d_in[0];
    const float* h_child = (const float*)d_in[1];
    const float* c_child = (const float*)d_in[2];
    const float* w_iou   = (const float*)d_in[3];
    const float* b_iou   = (const float*)d_in[4];
    const float* w_f     = (const float*)d_in[5];
    const float* b_f     = (const float*)d_in[6];
    const float* u_iou   = (const float*)d_in[7];
    const float* u_f     = (const float*)d_in[8];
    const int*   esrc    = (const int*)d_in[9];
    const int*   edst    = (const int*)d_in[10];
    float* out = (float*)d_out;

    static bool configured = false;
    if (!configured) {
        cudaFuncSetAttribute(k_mma<0>, cudaFuncAttributeMaxDynamicSharedMemorySize, SMEM_MMA);
        cudaFuncSetAttribute(k_mma<1>, cudaFuncAttributeMaxDynamicSharedMemorySize, SMEM_MMA);
        cudaFuncSetAttribute(k_mma<2>, cudaFuncAttributeMaxDynamicSharedMemorySize, SMEM_MMA);
        configured = true;
    }

    const int total4 = NN * HS / 4;

    k_prep<<<131072 / 256, 256>>>(w_iou, w_f, u_iou, u_f, b_iou, b_f);
    k_zero<<<(total4 + 255) / 256, 256>>>();
    k_mma<0><<<ROW_TILES, 256, SMEM_MMA>>>(x);        // x -> g_xa16 (i|o|u) + g_xf16 (f)
    k_mma<1><<<ROW_TILES, 256, SMEM_MMA>>>(h_child);  // h_child -> g_hu16
    k_edge<<<(NE * 32) / 256, 256>>>(h_child, c_child, esrc, edst);
    k_mma<2><<<ROW_TILES, 256, SMEM_MMA>>>(nullptr);  // g_hsum16 -> g_uh16 (1-term)
    k_final<<<(NN * 64 + 255) / 256, 256>>>(out);
}